// round 6
// baseline (speedup 1.0000x reference)
#include <cuda_runtime.h>
#include <cstdint>

// Haar DWT level-1 on x: (8, 64, 512, 512) fp32 -> 4 quadrants (8,64,256,256)
// concatenated in d_out as [ll | lh | hl | hh].
//
// Best-measured shape (R5): per thread one 2x8 input patch (4x float4
// streaming loads, front-batched) -> four 2x2 Haar butterflies -> one float4
// store per quadrant. Flat one-shot launch, 512-thread blocks, regs=32.
// This round: stores use __stwt (write-through) instead of __stcs to smooth
// the L2->DRAM writeback stream on a pure streaming kernel.
//
// planes P = 512, H = W = 512, outH = outW = 256
// total threads = 512 * 256 * 64 = 8,388,608 = 16384 blocks x 512

__global__ __launch_bounds__(512, 4)
void haar_dwt_kernel(const float* __restrict__ in, float* __restrict__ out) {
    const unsigned idx = blockIdx.x * 512u + threadIdx.x;   // < 8,388,608
    const unsigned tx = idx & 63u;             // group of 4 output cols (0..63)
    const unsigned oy = (idx >> 6) & 255u;     // output row (0..255)
    const unsigned p  = idx >> 14;             // plane (0..511)

    // Input: rows 2*oy and 2*oy+1 of plane p; cols 8tx..8tx+7 (two float4 each).
    const float4* __restrict__ in4 =
        reinterpret_cast<const float4*>(in) + ((size_t)p * 512u + 2u * oy) * 128u + 2u * tx;
    const float4 r0a = __ldcs(in4 + 0);      // row 2*oy,   cols 8tx..8tx+3
    const float4 r0b = __ldcs(in4 + 1);      // row 2*oy,   cols 8tx+4..8tx+7
    const float4 r1a = __ldcs(in4 + 128);    // row 2*oy+1, cols 8tx..8tx+3
    const float4 r1b = __ldcs(in4 + 129);    // row 2*oy+1, cols 8tx+4..8tx+7

    float4 ll, lh, hl, hh;

    {   // block 0: cols 8tx, 8tx+1
        const float a = r0a.x, b = r0a.y, c = r1a.x, d = r1a.y;
        ll.x = ( a + b + c + d) * 0.5f;  lh.x = (-a - b + c + d) * 0.5f;
        hl.x = (-a + b - c + d) * 0.5f;  hh.x = ( a - b - c + d) * 0.5f;
    }
    {   // block 1: cols 8tx+2, 8tx+3
        const float a = r0a.z, b = r0a.w, c = r1a.z, d = r1a.w;
        ll.y = ( a + b + c + d) * 0.5f;  lh.y = (-a - b + c + d) * 0.5f;
        hl.y = (-a + b - c + d) * 0.5f;  hh.y = ( a - b - c + d) * 0.5f;
    }
    {   // block 2: cols 8tx+4, 8tx+5
        const float a = r0b.x, b = r0b.y, c = r1b.x, d = r1b.y;
        ll.z = ( a + b + c + d) * 0.5f;  lh.z = (-a - b + c + d) * 0.5f;
        hl.z = (-a + b - c + d) * 0.5f;  hh.z = ( a - b - c + d) * 0.5f;
    }
    {   // block 3: cols 8tx+6, 8tx+7
        const float a = r0b.z, b = r0b.w, c = r1b.z, d = r1b.w;
        ll.w = ( a + b + c + d) * 0.5f;  lh.w = (-a - b + c + d) * 0.5f;
        hl.w = (-a + b - c + d) * 0.5f;  hh.w = ( a - b - c + d) * 0.5f;
    }

    // Output: element offset within a quadrant; multiple of 4 -> float4 aligned.
    const size_t qsize = (size_t)512u * 256u * 256u;               // 33,554,432
    const size_t obase = (((size_t)p * 256u + oy) * 256u) + 4u * tx;

    __stwt(reinterpret_cast<float4*>(out + 0 * qsize + obase), ll);
    __stwt(reinterpret_cast<float4*>(out + 1 * qsize + obase), lh);
    __stwt(reinterpret_cast<float4*>(out + 2 * qsize + obase), hl);
    __stwt(reinterpret_cast<float4*>(out + 3 * qsize + obase), hh);
}

extern "C" void kernel_launch(void* const* d_in, const int* in_sizes, int n_in,
                              void* d_out, int out_size) {
    const float* x = (const float*)d_in[0];
    float* out = (float*)d_out;
    haar_dwt_kernel<<<16384, 512>>>(x, out);
}

// round 7
// speedup vs baseline: 1.0173x; 1.0173x over previous
#include <cuda_runtime.h>
#include <cstdint>

// Haar DWT level-1 on x: (8, 64, 512, 512) fp32 -> 4 quadrants (8,64,256,256)
// concatenated in d_out as [ll | lh | hl | hh].
//
// Final config (HBM-wall verified across 6 schedule variants, all 6.67-6.81 TB/s):
//   per thread: one 2x8 input patch (4x float4 __ldcs, front-batched, MLP=4)
//   -> four 2x2 Haar butterflies -> one float4 __stcs per quadrant.
//   Flat one-shot launch (persistent loop measured worse: loop-carried register
//   reuse collapses per-warp MLP). __stwt measured worse (breaks L2 write
//   combining). Block size 256->512 helped slightly; this round: 1024.
//
// planes P = 512, H = W = 512, outH = outW = 256
// total threads = 512 * 256 * 64 = 8,388,608 = 8192 blocks x 1024

__global__ __launch_bounds__(1024, 2)
void haar_dwt_kernel(const float* __restrict__ in, float* __restrict__ out) {
    const unsigned idx = blockIdx.x * 1024u + threadIdx.x;   // < 8,388,608
    const unsigned tx = idx & 63u;             // group of 4 output cols (0..63)
    const unsigned oy = (idx >> 6) & 255u;     // output row (0..255)
    const unsigned p  = idx >> 14;             // plane (0..511)

    // Input: rows 2*oy and 2*oy+1 of plane p; cols 8tx..8tx+7 (two float4 each).
    const float4* __restrict__ in4 =
        reinterpret_cast<const float4*>(in) + ((size_t)p * 512u + 2u * oy) * 128u + 2u * tx;
    const float4 r0a = __ldcs(in4 + 0);      // row 2*oy,   cols 8tx..8tx+3
    const float4 r0b = __ldcs(in4 + 1);      // row 2*oy,   cols 8tx+4..8tx+7
    const float4 r1a = __ldcs(in4 + 128);    // row 2*oy+1, cols 8tx..8tx+3
    const float4 r1b = __ldcs(in4 + 129);    // row 2*oy+1, cols 8tx+4..8tx+7

    float4 ll, lh, hl, hh;

    {   // block 0: cols 8tx, 8tx+1
        const float a = r0a.x, b = r0a.y, c = r1a.x, d = r1a.y;
        ll.x = ( a + b + c + d) * 0.5f;  lh.x = (-a - b + c + d) * 0.5f;
        hl.x = (-a + b - c + d) * 0.5f;  hh.x = ( a - b - c + d) * 0.5f;
    }
    {   // block 1: cols 8tx+2, 8tx+3
        const float a = r0a.z, b = r0a.w, c = r1a.z, d = r1a.w;
        ll.y = ( a + b + c + d) * 0.5f;  lh.y = (-a - b + c + d) * 0.5f;
        hl.y = (-a + b - c + d) * 0.5f;  hh.y = ( a - b - c + d) * 0.5f;
    }
    {   // block 2: cols 8tx+4, 8tx+5
        const float a = r0b.x, b = r0b.y, c = r1b.x, d = r1b.y;
        ll.z = ( a + b + c + d) * 0.5f;  lh.z = (-a - b + c + d) * 0.5f;
        hl.z = (-a + b - c + d) * 0.5f;  hh.z = ( a - b - c + d) * 0.5f;
    }
    {   // block 3: cols 8tx+6, 8tx+7
        const float a = r0b.z, b = r0b.w, c = r1b.z, d = r1b.w;
        ll.w = ( a + b + c + d) * 0.5f;  lh.w = (-a - b + c + d) * 0.5f;
        hl.w = (-a + b - c + d) * 0.5f;  hh.w = ( a - b - c + d) * 0.5f;
    }

    // Output: element offset within a quadrant; multiple of 4 -> float4 aligned.
    const size_t qsize = (size_t)512u * 256u * 256u;               // 33,554,432
    const size_t obase = (((size_t)p * 256u + oy) * 256u) + 4u * tx;

    __stcs(reinterpret_cast<float4*>(out + 0 * qsize + obase), ll);
    __stcs(reinterpret_cast<float4*>(out + 1 * qsize + obase), lh);
    __stcs(reinterpret_cast<float4*>(out + 2 * qsize + obase), hl);
    __stcs(reinterpret_cast<float4*>(out + 3 * qsize + obase), hh);
}

extern "C" void kernel_launch(void* const* d_in, const int* in_sizes, int n_in,
                              void* d_out, int out_size) {
    const float* x = (const float*)d_in[0];
    float* out = (float*)d_out;
    haar_dwt_kernel<<<8192, 1024>>>(x, out);
}

// round 8
// speedup vs baseline: 1.0234x; 1.0059x over previous
#include <cuda_runtime.h>
#include <cstdint>

// Haar DWT level-1 on x: (8, 64, 512, 512) fp32 -> 4 quadrants (8,64,256,256)
// concatenated in d_out as [ll | lh | hl | hh].
//
// FINAL (R5 config). HBM-roofline-bound: 1.074 GB mandatory traffic at
// ~6.8 TB/s (85% of 8 TB/s spec). Verified wall across 7 schedule variants:
//   - vector width / per-thread MLP 2/4/8: 4 loads (2x8 patch) best
//   - persistent grid: WORSE (loop-carried reg reuse collapses per-warp MLP)
//   - __stwt: WORSE (breaks L2 write combining); __stcs both ways best
//   - block 256/512/1024: 512 best by a hair
//
// Per thread: one 2x8 input patch (4x float4 __ldcs, front-batched) ->
// four 2x2 Haar butterflies -> one float4 __stcs per quadrant.
// total threads = 512 * 256 * 64 = 8,388,608 = 16384 blocks x 512

__global__ __launch_bounds__(512, 4)
void haar_dwt_kernel(const float* __restrict__ in, float* __restrict__ out) {
    const unsigned idx = blockIdx.x * 512u + threadIdx.x;   // < 8,388,608
    const unsigned tx = idx & 63u;             // group of 4 output cols (0..63)
    const unsigned oy = (idx >> 6) & 255u;     // output row (0..255)
    const unsigned p  = idx >> 14;             // plane (0..511)

    // Input: rows 2*oy and 2*oy+1 of plane p; cols 8tx..8tx+7 (two float4 each).
    const float4* __restrict__ in4 =
        reinterpret_cast<const float4*>(in) + ((size_t)p * 512u + 2u * oy) * 128u + 2u * tx;
    const float4 r0a = __ldcs(in4 + 0);      // row 2*oy,   cols 8tx..8tx+3
    const float4 r0b = __ldcs(in4 + 1);      // row 2*oy,   cols 8tx+4..8tx+7
    const float4 r1a = __ldcs(in4 + 128);    // row 2*oy+1, cols 8tx..8tx+3
    const float4 r1b = __ldcs(in4 + 129);    // row 2*oy+1, cols 8tx+4..8tx+7

    float4 ll, lh, hl, hh;

    {   // block 0: cols 8tx, 8tx+1
        const float a = r0a.x, b = r0a.y, c = r1a.x, d = r1a.y;
        ll.x = ( a + b + c + d) * 0.5f;  lh.x = (-a - b + c + d) * 0.5f;
        hl.x = (-a + b - c + d) * 0.5f;  hh.x = ( a - b - c + d) * 0.5f;
    }
    {   // block 1: cols 8tx+2, 8tx+3
        const float a = r0a.z, b = r0a.w, c = r1a.z, d = r1a.w;
        ll.y = ( a + b + c + d) * 0.5f;  lh.y = (-a - b + c + d) * 0.5f;
        hl.y = (-a + b - c + d) * 0.5f;  hh.y = ( a - b - c + d) * 0.5f;
    }
    {   // block 2: cols 8tx+4, 8tx+5
        const float a = r0b.x, b = r0b.y, c = r1b.x, d = r1b.y;
        ll.z = ( a + b + c + d) * 0.5f;  lh.z = (-a - b + c + d) * 0.5f;
        hl.z = (-a + b - c + d) * 0.5f;  hh.z = ( a - b - c + d) * 0.5f;
    }
    {   // block 3: cols 8tx+6, 8tx+7
        const float a = r0b.z, b = r0b.w, c = r1b.z, d = r1b.w;
        ll.w = ( a + b + c + d) * 0.5f;  lh.w = (-a - b + c + d) * 0.5f;
        hl.w = (-a + b - c + d) * 0.5f;  hh.w = ( a - b - c + d) * 0.5f;
    }

    // Output: element offset within a quadrant; multiple of 4 -> float4 aligned.
    const size_t qsize = (size_t)512u * 256u * 256u;               // 33,554,432
    const size_t obase = (((size_t)p * 256u + oy) * 256u) + 4u * tx;

    __stcs(reinterpret_cast<float4*>(out + 0 * qsize + obase), ll);
    __stcs(reinterpret_cast<float4*>(out + 1 * qsize + obase), lh);
    __stcs(reinterpret_cast<float4*>(out + 2 * qsize + obase), hl);
    __stcs(reinterpret_cast<float4*>(out + 3 * qsize + obase), hh);
}

extern "C" void kernel_launch(void* const* d_in, const int* in_sizes, int n_in,
                              void* d_out, int out_size) {
    const float* x = (const float*)d_in[0];
    float* out = (float*)d_out;
    haar_dwt_kernel<<<16384, 512>>>(x, out);
}

// round 9
// speedup vs baseline: 1.0236x; 1.0002x over previous
#include <cuda_runtime.h>
#include <cstdint>

// Haar DWT level-1 on x: (8, 64, 512, 512) fp32 -> 4 quadrants (8,64,256,256)
// concatenated in d_out as [ll | lh | hl | hh].
//
// FINAL — HBM-roofline-bound and converged. 1.074 GB mandatory traffic at
// 6.81 TB/s (85.1% of 8 TB/s spec), reproduced to 0.02% across two runs.
// Sweep evidence (8 variants): vector width, per-thread MLP (2/4/8), block
// size (256/512/1024), persistent vs flat, and load/store cache policies all
// land 6.67-6.81 TB/s; persistent grid (-13%) and __stwt (-1.5%) were the
// only material movers, both negative. Compute pipes <10% busy.
//
// Per thread: one 2x8 input patch (4x float4 __ldcs, front-batched, MLP=4)
// -> four 2x2 Haar butterflies -> one float4 __stcs per quadrant.
// total threads = 512 * 256 * 64 = 8,388,608 = 16384 blocks x 512

__global__ __launch_bounds__(512, 4)
void haar_dwt_kernel(const float* __restrict__ in, float* __restrict__ out) {
    const unsigned idx = blockIdx.x * 512u + threadIdx.x;   // < 8,388,608
    const unsigned tx = idx & 63u;             // group of 4 output cols (0..63)
    const unsigned oy = (idx >> 6) & 255u;     // output row (0..255)
    const unsigned p  = idx >> 14;             // plane (0..511)

    // Input: rows 2*oy and 2*oy+1 of plane p; cols 8tx..8tx+7 (two float4 each).
    const float4* __restrict__ in4 =
        reinterpret_cast<const float4*>(in) + ((size_t)p * 512u + 2u * oy) * 128u + 2u * tx;
    const float4 r0a = __ldcs(in4 + 0);      // row 2*oy,   cols 8tx..8tx+3
    const float4 r0b = __ldcs(in4 + 1);      // row 2*oy,   cols 8tx+4..8tx+7
    const float4 r1a = __ldcs(in4 + 128);    // row 2*oy+1, cols 8tx..8tx+3
    const float4 r1b = __ldcs(in4 + 129);    // row 2*oy+1, cols 8tx+4..8tx+7

    float4 ll, lh, hl, hh;

    {   // block 0: cols 8tx, 8tx+1
        const float a = r0a.x, b = r0a.y, c = r1a.x, d = r1a.y;
        ll.x = ( a + b + c + d) * 0.5f;  lh.x = (-a - b + c + d) * 0.5f;
        hl.x = (-a + b - c + d) * 0.5f;  hh.x = ( a - b - c + d) * 0.5f;
    }
    {   // block 1: cols 8tx+2, 8tx+3
        const float a = r0a.z, b = r0a.w, c = r1a.z, d = r1a.w;
        ll.y = ( a + b + c + d) * 0.5f;  lh.y = (-a - b + c + d) * 0.5f;
        hl.y = (-a + b - c + d) * 0.5f;  hh.y = ( a - b - c + d) * 0.5f;
    }
    {   // block 2: cols 8tx+4, 8tx+5
        const float a = r0b.x, b = r0b.y, c = r1b.x, d = r1b.y;
        ll.z = ( a + b + c + d) * 0.5f;  lh.z = (-a - b + c + d) * 0.5f;
        hl.z = (-a + b - c + d) * 0.5f;  hh.z = ( a - b - c + d) * 0.5f;
    }
    {   // block 3: cols 8tx+6, 8tx+7
        const float a = r0b.z, b = r0b.w, c = r1b.z, d = r1b.w;
        ll.w = ( a + b + c + d) * 0.5f;  lh.w = (-a - b + c + d) * 0.5f;
        hl.w = (-a + b - c + d) * 0.5f;  hh.w = ( a - b - c + d) * 0.5f;
    }

    // Output: element offset within a quadrant; multiple of 4 -> float4 aligned.
    const size_t qsize = (size_t)512u * 256u * 256u;               // 33,554,432
    const size_t obase = (((size_t)p * 256u + oy) * 256u) + 4u * tx;

    __stcs(reinterpret_cast<float4*>(out + 0 * qsize + obase), ll);
    __stcs(reinterpret_cast<float4*>(out + 1 * qsize + obase), lh);
    __stcs(reinterpret_cast<float4*>(out + 2 * qsize + obase), hl);
    __stcs(reinterpret_cast<float4*>(out + 3 * qsize + obase), hh);
}

extern "C" void kernel_launch(void* const* d_in, const int* in_sizes, int n_in,
                              void* d_out, int out_size) {
    const float* x = (const float*)d_in[0];
    float* out = (float*)d_out;
    haar_dwt_kernel<<<16384, 512>>>(x, out);
}